// round 1
// baseline (speedup 1.0000x reference)
#include <cuda_runtime.h>
#include <math.h>

#define B_  4
#define L_  2048
#define D_  1024
#define H_  16
#define DH  64
#define M_  (B_*L_)        /* 8192 */
#define NEGINF_SUB 1e7f

// -------------------- scratch (static device globals; no allocation) --------------------
__device__ float g_qpe[M_*D_];   // q + pe
__device__ float g_kpe[M_*D_];   // k + pe
__device__ float g_Qh[M_*D_];    // [B,H,L,DH]
__device__ float g_Kh[M_*D_];    // [B,H,L,DH]
__device__ float g_Vh[M_*D_];    // [B,H,L,DH]
__device__ float g_attn[M_*D_];  // [B,L,D]

// -------------------- PE add --------------------
// one thread per (row, freq): writes sin/cos pair for q and k
__global__ void pe_add_kernel(const float* __restrict__ q, const float* __restrict__ k) {
    int i = blockIdx.x * blockDim.x + threadIdx.x;
    const int NF = D_ / 2;  // 512
    if (i >= M_ * NF) return;
    int row = i / NF;
    int f   = i - row * NF;
    int l   = row & (L_ - 1);
    // period = 10000^(-f/512)
    const float kC = 9.210340371976184f / 512.0f;  // ln(10000)/512
    float ang = (float)l * expf(-(float)f * kC);
    float s, c;
    sincosf(ang, &s, &c);
    int base = row * D_ + 2 * f;
    g_qpe[base]     = q[base]     + s;
    g_qpe[base + 1] = q[base + 1] + c;
    g_kpe[base]     = k[base]     + s;
    g_kpe[base + 1] = k[base + 1] + c;
}

// -------------------- SGEMM: C = A[M,1024] @ W[1024,1024] + bias --------------------
// BM=BN=128, BK=8, 256 threads, 8x8 per thread.
// HEADLAYOUT=1: write C[m, n] -> out[((b*H + n/64)*L + l)*64 + n%64]
template <int HEADLAYOUT>
__global__ void __launch_bounds__(256, 2)
sgemm_bias(const float* __restrict__ A, const float* __restrict__ W,
           const float* __restrict__ bias, float* __restrict__ C) {
    const int BM = 128, BN = 128, BK = 8;
    const int K = D_;
    __shared__ __align__(16) float sA[BK][BM + 4];   // stride 132 -> conflict-free stores
    __shared__ __align__(16) float sB[BK][BN];

    int tid = threadIdx.x;
    int bm = blockIdx.y, bn = blockIdx.x;
    int ty = tid >> 4, tx = tid & 15;

    float acc[8][8];
#pragma unroll
    for (int i = 0; i < 8; i++)
#pragma unroll
        for (int j = 0; j < 8; j++) acc[i][j] = 0.0f;

    for (int k0 = 0; k0 < K; k0 += BK) {
#pragma unroll
        for (int i = 0; i < 4; i++) {       // A tile: 128x8
            int idx = i * 256 + tid;
            int kk = idx & 7;
            int rr = idx >> 3;
            sA[kk][rr] = A[(bm * BM + rr) * K + (k0 + kk)];
        }
#pragma unroll
        for (int i = 0; i < 4; i++) {       // B tile: 8x128
            int idx = i * 256 + tid;
            int cc = idx & 127;
            int kk = idx >> 7;
            sB[kk][cc] = W[(k0 + kk) * D_ + bn * BN + cc];
        }
        __syncthreads();
#pragma unroll
        for (int kk = 0; kk < BK; kk++) {
            float a[8], b[8];
            *(float4*)&a[0] = *(const float4*)&sA[kk][ty * 8];
            *(float4*)&a[4] = *(const float4*)&sA[kk][ty * 8 + 4];
            *(float4*)&b[0] = *(const float4*)&sB[kk][tx * 8];
            *(float4*)&b[4] = *(const float4*)&sB[kk][tx * 8 + 4];
#pragma unroll
            for (int i = 0; i < 8; i++)
#pragma unroll
                for (int j = 0; j < 8; j++)
                    acc[i][j] = fmaf(a[i], b[j], acc[i][j]);
        }
        __syncthreads();
    }

#pragma unroll
    for (int i = 0; i < 8; i++) {
        int m = bm * BM + ty * 8 + i;
        int bidx = m / L_;
        int l = m - bidx * L_;
#pragma unroll
        for (int j = 0; j < 8; j++) {
            int n = bn * BN + tx * 8 + j;
            float v = acc[i][j] + bias[n];
            if (HEADLAYOUT) {
                int h = n >> 6, dd = n & 63;
                C[((bidx * H_ + h) * L_ + l) * DH + dd] = v;
            } else {
                C[m * D_ + n] = v;
            }
        }
    }
}

// -------------------- fused causal flash attention --------------------
// grid (L/64, B*H), 256 threads, 64-row Q tile, d_head=64, fp32 online softmax.
#define SM_STRIDE 68
#define SMEM_ATTN (4 * 64 * SM_STRIDE * (int)sizeof(float))   // sQT, sKT, sV, sPT

__global__ void __launch_bounds__(256)
attn_kernel(const unsigned char* __restrict__ pad, float* __restrict__ out_attn) {
    extern __shared__ __align__(16) float sm[];
    float* sQT = sm;                       // [kk][r]
    float* sKT = sQT + 64 * SM_STRIDE;     // [kk][c]
    float* sV  = sKT + 64 * SM_STRIDE;     // [c][d]
    float* sPT = sV  + 64 * SM_STRIDE;     // [c][r]

    int tid = threadIdx.x;
    int ty = tid >> 4, tx = tid & 15;
    int qt = blockIdx.x;
    int bh = blockIdx.y;
    int b = bh / H_;
    int h = bh - b * H_;

    const float* Q  = g_Qh + (size_t)bh * L_ * DH;
    const float* Kp = g_Kh + (size_t)bh * L_ * DH;
    const float* Vp = g_Vh + (size_t)bh * L_ * DH;

    // load Q tile transposed: sQT[kk][r]
#pragma unroll
    for (int i = 0; i < 4; i++) {
        int f = i * 256 + tid;             // 0..1023 float4s
        int r = f >> 4;
        int kk4 = (f & 15) * 4;
        float4 v = *(const float4*)&Q[(qt * 64 + r) * DH + kk4];
        sQT[(kk4 + 0) * SM_STRIDE + r] = v.x;
        sQT[(kk4 + 1) * SM_STRIDE + r] = v.y;
        sQT[(kk4 + 2) * SM_STRIDE + r] = v.z;
        sQT[(kk4 + 3) * SM_STRIDE + r] = v.w;
    }

    float m_i[4], l_i[4], o[4][4];
#pragma unroll
    for (int i = 0; i < 4; i++) {
        m_i[i] = -1e30f;
        l_i[i] = 0.0f;
#pragma unroll
        for (int j = 0; j < 4; j++) o[i][j] = 0.0f;
    }
    const float scale = 0.125f;  // 1/sqrt(64)

    for (int kt = 0; kt <= qt; kt++) {
        __syncthreads();   // prior PV done (and first iter: Q stores done)
        // load K (transposed) and V tiles
#pragma unroll
        for (int i = 0; i < 4; i++) {
            int f = i * 256 + tid;
            int c = f >> 4;
            int kk4 = (f & 15) * 4;
            float4 kv = *(const float4*)&Kp[(kt * 64 + c) * DH + kk4];
            sKT[(kk4 + 0) * SM_STRIDE + c] = kv.x;
            sKT[(kk4 + 1) * SM_STRIDE + c] = kv.y;
            sKT[(kk4 + 2) * SM_STRIDE + c] = kv.z;
            sKT[(kk4 + 3) * SM_STRIDE + c] = kv.w;
            float4 vv = *(const float4*)&Vp[(kt * 64 + c) * DH + kk4];
            *(float4*)&sV[c * SM_STRIDE + kk4] = vv;
        }
        __syncthreads();

        // S = Q K^T (4x4 frag per thread)
        float s[4][4];
#pragma unroll
        for (int i = 0; i < 4; i++)
#pragma unroll
            for (int j = 0; j < 4; j++) s[i][j] = 0.0f;
#pragma unroll 8
        for (int kk = 0; kk < 64; kk++) {
            float4 qv = *(const float4*)&sQT[kk * SM_STRIDE + ty * 4];
            float4 kv = *(const float4*)&sKT[kk * SM_STRIDE + tx * 4];
            float qa[4] = {qv.x, qv.y, qv.z, qv.w};
            float ka[4] = {kv.x, kv.y, kv.z, kv.w};
#pragma unroll
            for (int i = 0; i < 4; i++)
#pragma unroll
                for (int j = 0; j < 4; j++)
                    s[i][j] = fmaf(qa[i], ka[j], s[i][j]);
        }

        // scale + masks + row max
        float rmax[4];
#pragma unroll
        for (int i = 0; i < 4; i++) rmax[i] = -1e30f;
#pragma unroll
        for (int j = 0; j < 4; j++) {
            int cg = kt * 64 + tx * 4 + j;
            float msub = (pad[b * L_ + cg] != 0) ? NEGINF_SUB : 0.0f;
#pragma unroll
            for (int i = 0; i < 4; i++) {
                int rg = qt * 64 + ty * 4 + i;
                float v = s[i][j] * scale - msub;
                if (cg > rg) v -= NEGINF_SUB;   // causal
                s[i][j] = v;
                rmax[i] = fmaxf(rmax[i], v);
            }
        }
#pragma unroll
        for (int off = 1; off < 16; off <<= 1)
#pragma unroll
            for (int i = 0; i < 4; i++)
                rmax[i] = fmaxf(rmax[i], __shfl_xor_sync(0xffffffffu, rmax[i], off));

        float corr[4], rsum[4];
#pragma unroll
        for (int i = 0; i < 4; i++) {
            float mnew = fmaxf(m_i[i], rmax[i]);
            corr[i] = expf(m_i[i] - mnew);
            m_i[i] = mnew;
            float rs = 0.0f;
#pragma unroll
            for (int j = 0; j < 4; j++) {
                s[i][j] = expf(s[i][j] - mnew);
                rs += s[i][j];
            }
            rsum[i] = rs;
        }
#pragma unroll
        for (int off = 1; off < 16; off <<= 1)
#pragma unroll
            for (int i = 0; i < 4; i++)
                rsum[i] += __shfl_xor_sync(0xffffffffu, rsum[i], off);
#pragma unroll
        for (int i = 0; i < 4; i++) {
            l_i[i] = l_i[i] * corr[i] + rsum[i];
#pragma unroll
            for (int j = 0; j < 4; j++) o[i][j] *= corr[i];
        }

        // write P transposed: sPT[c][r]
#pragma unroll
        for (int i = 0; i < 4; i++)
#pragma unroll
            for (int j = 0; j < 4; j++)
                sPT[(tx * 4 + j) * SM_STRIDE + (ty * 4 + i)] = s[i][j];
        __syncthreads();

        // O += P V
#pragma unroll 8
        for (int c = 0; c < 64; c++) {
            float4 pv = *(const float4*)&sPT[c * SM_STRIDE + ty * 4];
            float4 vv = *(const float4*)&sV[c * SM_STRIDE + tx * 4];
            float pa[4] = {pv.x, pv.y, pv.z, pv.w};
            float va[4] = {vv.x, vv.y, vv.z, vv.w};
#pragma unroll
            for (int i = 0; i < 4; i++)
#pragma unroll
                for (int j = 0; j < 4; j++)
                    o[i][j] = fmaf(pa[i], va[j], o[i][j]);
        }
    }

    // normalize + write to [B, L, D]
#pragma unroll
    for (int i = 0; i < 4; i++) {
        float inv = 1.0f / l_i[i];
        int qrow = qt * 64 + ty * 4 + i;
        float4 ov = make_float4(o[i][0] * inv, o[i][1] * inv, o[i][2] * inv, o[i][3] * inv);
        *(float4*)&out_attn[(size_t)(b * L_ + qrow) * D_ + h * DH + tx * 4] = ov;
    }
}

// -------------------- launch --------------------
extern "C" void kernel_launch(void* const* d_in, const int* in_sizes, int n_in,
                              void* d_out, int out_size) {
    const float* q  = (const float*)d_in[0];
    const float* k  = (const float*)d_in[1];
    const float* v  = (const float*)d_in[2];
    const unsigned char* pad = (const unsigned char*)d_in[3];
    const float* Wq = (const float*)d_in[4];
    const float* bq = (const float*)d_in[5];
    const float* Wk = (const float*)d_in[6];
    const float* bk = (const float*)d_in[7];
    const float* Wv = (const float*)d_in[8];
    const float* bv = (const float*)d_in[9];
    const float* Wo = (const float*)d_in[10];
    const float* bo = (const float*)d_in[11];
    float* out = (float*)d_out;

    float *p_qpe, *p_kpe, *p_Qh, *p_Kh, *p_Vh, *p_attn;
    cudaGetSymbolAddress((void**)&p_qpe,  g_qpe);
    cudaGetSymbolAddress((void**)&p_kpe,  g_kpe);
    cudaGetSymbolAddress((void**)&p_Qh,   g_Qh);
    cudaGetSymbolAddress((void**)&p_Kh,   g_Kh);
    cudaGetSymbolAddress((void**)&p_Vh,   g_Vh);
    cudaGetSymbolAddress((void**)&p_attn, g_attn);

    cudaFuncSetAttribute(attn_kernel, cudaFuncAttributeMaxDynamicSharedMemorySize, SMEM_ATTN);

    // 1) positional encodings
    int pe_threads = M_ * (D_ / 2);
    pe_add_kernel<<<(pe_threads + 255) / 256, 256>>>(q, k);

    // 2) QKV projections -> head layout
    dim3 gg(D_ / 128, M_ / 128), blk(256);
    sgemm_bias<1><<<gg, blk>>>(p_qpe, Wq, bq, p_Qh);
    sgemm_bias<1><<<gg, blk>>>(p_kpe, Wk, bk, p_Kh);
    sgemm_bias<1><<<gg, blk>>>(v,     Wv, bv, p_Vh);

    // 3) fused causal attention
    attn_kernel<<<dim3(L_ / 64, B_ * H_), 256, SMEM_ATTN>>>(pad, p_attn);

    // 4) output projection -> d_out
    sgemm_bias<0><<<gg, blk>>>(p_attn, Wo, bo, out);
}

// round 2
// speedup vs baseline: 3.1252x; 3.1252x over previous
#include <cuda_runtime.h>
#include <math.h>

#define B_  4
#define L_  2048
#define D_  1024
#define H_  16
#define DH  64
#define M_  (B_*L_)        /* 8192 */
#define NEG 1e7f

// -------------------- scratch --------------------
__device__ float g_qpe[M_*D_];
__device__ float g_kpe[M_*D_];
__device__ float g_Qh[M_*D_];    // [B,H,L,DH]
__device__ float g_Kh[M_*D_];
__device__ float g_Vh[M_*D_];
__device__ float g_attn[M_*D_];  // [B,L,D]

// -------------------- helpers --------------------
__device__ __forceinline__ unsigned f2tf(float x){
    unsigned r; asm("cvt.rna.tf32.f32 %0, %1;" : "=r"(r) : "f"(x)); return r;
}
// D += A(16x8,row) * B(8x8,col); tf32 in, fp32 acc
__device__ __forceinline__ void mma8(float* c, const unsigned* a, const unsigned* b){
    asm volatile("mma.sync.aligned.m16n8k8.row.col.f32.tf32.tf32.f32 "
        "{%0,%1,%2,%3}, {%4,%5,%6,%7}, {%8,%9}, {%0,%1,%2,%3};"
        : "+f"(c[0]),"+f"(c[1]),"+f"(c[2]),"+f"(c[3])
        : "r"(a[0]),"r"(a[1]),"r"(a[2]),"r"(a[3]),"r"(b[0]),"r"(b[1]));
}

// -------------------- PE add --------------------
__global__ void pe_add_kernel(const float* __restrict__ q, const float* __restrict__ k) {
    int i = blockIdx.x * blockDim.x + threadIdx.x;
    const int NF = D_ / 2;
    if (i >= M_ * NF) return;
    int row = i / NF;
    int f   = i - row * NF;
    int l   = row & (L_ - 1);
    const float kC = 9.210340371976184f / 512.0f;
    float ang = (float)l * expf(-(float)f * kC);
    float s, c;
    sincosf(ang, &s, &c);
    int base = row * D_ + 2 * f;
    g_qpe[base]     = q[base]     + s;
    g_qpe[base + 1] = q[base + 1] + c;
    g_kpe[base]     = k[base]     + s;
    g_kpe[base + 1] = k[base + 1] + c;
}

// -------------------- tf32 GEMM: C = A[8192,1024] @ W[1024,1024] + bias --------------------
// 128x128x16 block tile, 8 warps (2x4), warp tile 64x32 (4x4 m16n8k8 mmas per k8)
#define SA 20     /* sA row stride (k dim 16 + pad 4): conflict-free a-frag reads */
#define SB 136    /* sB row stride (n dim 128 + pad 8): conflict-free b-frag reads */

template<int HEADLAYOUT>
__global__ void __launch_bounds__(256, 2)
gemm_tf32(const float* __restrict__ A, const float* __restrict__ W,
          const float* __restrict__ bias, float* __restrict__ C){
    __shared__ unsigned sA[2][128*SA];   // 20480 B
    __shared__ unsigned sB[2][16*SB];    // 17408 B
    int tid=threadIdx.x, lane=tid&31;
    int warp=tid>>5, wm=warp>>2, wn=warp&3;
    int bm=blockIdx.y*128, bn=blockIdx.x*128;

    float acc[4][4][4];
#pragma unroll
    for(int i=0;i<4;i++)
#pragma unroll
      for(int j=0;j<4;j++)
#pragma unroll
        for(int r=0;r<4;r++) acc[i][j][r]=0.f;

    float4 pa[2], pb[2];
    // prefetch k-tile 0
#pragma unroll
    for(int t=0;t<2;t++){
        int ia=t*256+tid; int ra=ia>>2, ca=ia&3;
        pa[t]=*(const float4*)&A[(size_t)(bm+ra)*D_ + ca*4];
        int rb=ia>>5, cb=ia&31;
        pb[t]=*(const float4*)&W[(size_t)rb*D_ + bn + cb*4];
    }
    auto store_tile=[&](int buf){
#pragma unroll
        for(int t=0;t<2;t++){
            int ia=t*256+tid; int ra=ia>>2, ca=ia&3;
            uint4 va; va.x=f2tf(pa[t].x); va.y=f2tf(pa[t].y); va.z=f2tf(pa[t].z); va.w=f2tf(pa[t].w);
            *(uint4*)&sA[buf][ra*SA+ca*4]=va;        // 80*ra+16*ca bytes: 16B aligned
            int rb=ia>>5, cb=ia&31;
            uint4 vb; vb.x=f2tf(pb[t].x); vb.y=f2tf(pb[t].y); vb.z=f2tf(pb[t].z); vb.w=f2tf(pb[t].w);
            *(uint4*)&sB[buf][rb*SB+cb*4]=vb;        // 544*rb+16*cb: 16B aligned
        }
    };
    store_tile(0);
    __syncthreads();

    for(int kt=0;kt<64;kt++){
        int cur=kt&1;
        if(kt<63){
            int k0=(kt+1)*16;
#pragma unroll
            for(int t=0;t<2;t++){
                int ia=t*256+tid; int ra=ia>>2, ca=ia&3;
                pa[t]=*(const float4*)&A[(size_t)(bm+ra)*D_ + k0 + ca*4];
                int rb=ia>>5, cb=ia&31;
                pb[t]=*(const float4*)&W[(size_t)(k0+rb)*D_ + bn + cb*4];
            }
        }
#pragma unroll
        for(int ks=0;ks<2;ks++){
            unsigned af[4][4], bf[4][2];
#pragma unroll
            for(int mt=0;mt<4;mt++){
                const unsigned* base=&sA[cur][(wm*64+mt*16)*SA + ks*8];
                af[mt][0]=base[(lane>>2)*SA + (lane&3)];
                af[mt][1]=base[((lane>>2)+8)*SA + (lane&3)];
                af[mt][2]=base[(lane>>2)*SA + (lane&3)+4];
                af[mt][3]=base[((lane>>2)+8)*SA + (lane&3)+4];
            }
#pragma unroll
            for(int nt=0;nt<4;nt++){
                const unsigned* base=&sB[cur][ks*8*SB + wn*32 + nt*8];
                bf[nt][0]=base[(lane&3)*SB + (lane>>2)];
                bf[nt][1]=base[((lane&3)+4)*SB + (lane>>2)];
            }
#pragma unroll
            for(int mt=0;mt<4;mt++)
#pragma unroll
              for(int nt=0;nt<4;nt++)
                mma8(acc[mt][nt], af[mt], bf[nt]);
        }
        if(kt<63){ store_tile(1-cur); __syncthreads(); }
    }

    // epilogue: bias + store (optionally to head layout)
#pragma unroll
    for(int mt=0;mt<4;mt++){
        int r0=bm + wm*64 + mt*16 + (lane>>2);
#pragma unroll
        for(int half=0;half<2;half++){
            int m=r0+half*8;
            int bidx=m>>11, l=m&(L_-1);
#pragma unroll
            for(int nt=0;nt<4;nt++){
                int n=bn + wn*32 + nt*8 + 2*(lane&3);
                float2 bb=*(const float2*)&bias[n];
                float2 ov=make_float2(acc[mt][nt][half*2+0]+bb.x,
                                      acc[mt][nt][half*2+1]+bb.y);
                if(HEADLAYOUT){
                    int h=n>>6, dd=n&63;
                    *(float2*)&C[(size_t)((bidx*H_+h)*L_+l)*DH + dd]=ov;
                } else {
                    *(float2*)&C[(size_t)m*D_+n]=ov;
                }
            }
        }
    }
}

// -------------------- tf32 flash attention --------------------
// Q tile 128 rows, K/V tiles 64, 8 warps = one m16 row-group each.
#define AST 68
#define ATTN_SMEM ((128*AST + 64*AST + 64*AST + 8*16*AST)*4 + 256)

__global__ void __launch_bounds__(256, 2)
attn_tf32(const unsigned char* __restrict__ pad, float* __restrict__ outp){
    extern __shared__ unsigned sm_u[];
    unsigned* sQ = sm_u;                 // [r][d] stride 68
    unsigned* sK = sQ + 128*AST;         // [kcol][d]
    unsigned* sV = sK + 64*AST;          // [k][d]
    unsigned* sP = sV + 64*AST;          // per warp [16][68]
    float* spad  = (float*)(sP + 8*16*AST);  // 64 mask values

    int tid=threadIdx.x, lane=tid&31, warp=tid>>5;
    int qt=blockIdx.x, bh=blockIdx.y;
    int b=bh>>4, h=bh&15;
    const float* Q = g_Qh + (size_t)bh*L_*DH;
    const float* K = g_Kh + (size_t)bh*L_*DH;
    const float* V = g_Vh + (size_t)bh*L_*DH;

    // load Q tile (once): 128x64 -> tf32 smem
#pragma unroll
    for(int t=0;t<8;t++){
        int idx=t*256+tid;              // 2048 float4
        int r=idx>>4, c4=idx&15;
        float4 v=*(const float4*)&Q[(size_t)(qt*128+r)*DH + c4*4];
        uint4 u; u.x=f2tf(v.x); u.y=f2tf(v.y); u.z=f2tf(v.z); u.w=f2tf(v.w);
        *(uint4*)&sQ[r*AST + c4*4]=u;   // 272r+16c: aligned
    }

    float m_[2]={-1e30f,-1e30f}, l_[2]={0.f,0.f};
    float o[8][4];
#pragma unroll
    for(int i=0;i<8;i++){o[i][0]=0.f;o[i][1]=0.f;o[i][2]=0.f;o[i][3]=0.f;}
    const float scale=0.125f;
    int r0g = qt*128 + warp*16 + (lane>>2);
    int r1g = r0g + 8;
    unsigned* pw = &sP[warp*16*AST];

    int nkt = 2*qt+2;
    for(int kt=0;kt<nkt;kt++){
        __syncthreads();   // K/V (and Q on first iter) safe to (re)write
#pragma unroll
        for(int t=0;t<4;t++){
            int idx=t*256+tid; int r=idx>>4, c4=idx&15;
            float4 kv=*(const float4*)&K[(size_t)(kt*64+r)*DH + c4*4];
            uint4 uk; uk.x=f2tf(kv.x); uk.y=f2tf(kv.y); uk.z=f2tf(kv.z); uk.w=f2tf(kv.w);
            *(uint4*)&sK[r*AST+c4*4]=uk;
            float4 vv=*(const float4*)&V[(size_t)(kt*64+r)*DH + c4*4];
            uint4 uv; uv.x=f2tf(vv.x); uv.y=f2tf(vv.y); uv.z=f2tf(vv.z); uv.w=f2tf(vv.w);
            *(uint4*)&sV[r*AST+c4*4]=uv;
        }
        if(tid<64) spad[tid] = pad[b*L_ + kt*64 + tid] ? NEG : 0.f;
        __syncthreads();

        // ---- S = Q K^T ----
        float s[8][4];
#pragma unroll
        for(int i=0;i<8;i++){s[i][0]=0.f;s[i][1]=0.f;s[i][2]=0.f;s[i][3]=0.f;}
#pragma unroll
        for(int ks=0;ks<8;ks++){
            unsigned a[4];
            const unsigned* qb=&sQ[(warp*16)*AST + ks*8];
            a[0]=qb[(lane>>2)*AST + (lane&3)];
            a[1]=qb[((lane>>2)+8)*AST + (lane&3)];
            a[2]=qb[(lane>>2)*AST + (lane&3)+4];
            a[3]=qb[((lane>>2)+8)*AST + (lane&3)+4];
#pragma unroll
            for(int nt=0;nt<8;nt++){
                unsigned bfr[2];
                const unsigned* kb=&sK[(nt*8+(lane>>2))*AST + ks*8];
                bfr[0]=kb[lane&3];
                bfr[1]=kb[(lane&3)+4];
                mma8(s[nt], a, bfr);
            }
        }

        // ---- scale + mask + online softmax ----
        float rmax0=-1e30f, rmax1=-1e30f;
#pragma unroll
        for(int nt=0;nt<8;nt++){
            int cl = nt*8 + 2*(lane&3);
            int c0 = kt*64 + cl, c1 = c0+1;
            float ms0=spad[cl], ms1=spad[cl+1];
            float v0=s[nt][0]*scale - ms0; if(c0>r0g) v0-=NEG;
            float v1=s[nt][1]*scale - ms1; if(c1>r0g) v1-=NEG;
            float v2=s[nt][2]*scale - ms0; if(c0>r1g) v2-=NEG;
            float v3=s[nt][3]*scale - ms1; if(c1>r1g) v3-=NEG;
            s[nt][0]=v0; s[nt][1]=v1; s[nt][2]=v2; s[nt][3]=v3;
            rmax0=fmaxf(rmax0,fmaxf(v0,v1));
            rmax1=fmaxf(rmax1,fmaxf(v2,v3));
        }
        rmax0=fmaxf(rmax0,__shfl_xor_sync(0xffffffffu,rmax0,1));
        rmax0=fmaxf(rmax0,__shfl_xor_sync(0xffffffffu,rmax0,2));
        rmax1=fmaxf(rmax1,__shfl_xor_sync(0xffffffffu,rmax1,1));
        rmax1=fmaxf(rmax1,__shfl_xor_sync(0xffffffffu,rmax1,2));

        float mn0=fmaxf(m_[0],rmax0), mn1=fmaxf(m_[1],rmax1);
        float corr0=__expf(m_[0]-mn0), corr1=__expf(m_[1]-mn1);
        m_[0]=mn0; m_[1]=mn1;
        float rs0=0.f, rs1=0.f;
#pragma unroll
        for(int nt=0;nt<8;nt++){
            s[nt][0]=__expf(s[nt][0]-mn0); rs0+=s[nt][0];
            s[nt][1]=__expf(s[nt][1]-mn0); rs0+=s[nt][1];
            s[nt][2]=__expf(s[nt][2]-mn1); rs1+=s[nt][2];
            s[nt][3]=__expf(s[nt][3]-mn1); rs1+=s[nt][3];
        }
        rs0+=__shfl_xor_sync(0xffffffffu,rs0,1);
        rs0+=__shfl_xor_sync(0xffffffffu,rs0,2);
        rs1+=__shfl_xor_sync(0xffffffffu,rs1,1);
        rs1+=__shfl_xor_sync(0xffffffffu,rs1,2);
        l_[0]=l_[0]*corr0+rs0; l_[1]=l_[1]*corr1+rs1;
#pragma unroll
        for(int nt=0;nt<8;nt++){
            o[nt][0]*=corr0; o[nt][1]*=corr0;
            o[nt][2]*=corr1; o[nt][3]*=corr1;
        }

        // ---- P -> warp-private smem (tf32) ----
#pragma unroll
        for(int nt=0;nt<8;nt++){
            int cl = nt*8 + 2*(lane&3);
            pw[(lane>>2)*AST + cl]     = f2tf(s[nt][0]);
            pw[(lane>>2)*AST + cl+1]   = f2tf(s[nt][1]);
            pw[((lane>>2)+8)*AST + cl]   = f2tf(s[nt][2]);
            pw[((lane>>2)+8)*AST + cl+1] = f2tf(s[nt][3]);
        }
        __syncwarp();

        // ---- O += P V ----
#pragma unroll
        for(int ks=0;ks<8;ks++){
            unsigned a[4];
            const unsigned* pb=&pw[ks*8];
            a[0]=pb[(lane>>2)*AST + (lane&3)];
            a[1]=pb[((lane>>2)+8)*AST + (lane&3)];
            a[2]=pb[(lane>>2)*AST + (lane&3)+4];
            a[3]=pb[((lane>>2)+8)*AST + (lane&3)+4];
#pragma unroll
            for(int nt=0;nt<8;nt++){
                unsigned bfr[2];
                bfr[0]=sV[(ks*8+(lane&3))*AST + nt*8 + (lane>>2)];
                bfr[1]=sV[(ks*8+(lane&3)+4)*AST + nt*8 + (lane>>2)];
                mma8(o[nt], a, bfr);
            }
        }
    }

    // ---- normalize + write [B,L,D] ----
    float inv0=1.f/l_[0], inv1=1.f/l_[1];
#pragma unroll
    for(int nt=0;nt<8;nt++){
        int dd = nt*8 + 2*(lane&3);
        float2 v0=make_float2(o[nt][0]*inv0, o[nt][1]*inv0);
        float2 v1=make_float2(o[nt][2]*inv1, o[nt][3]*inv1);
        *(float2*)&outp[(size_t)(b*L_+r0g)*D_ + h*DH + dd]=v0;
        *(float2*)&outp[(size_t)(b*L_+r1g)*D_ + h*DH + dd]=v1;
    }
}

// -------------------- launch --------------------
extern "C" void kernel_launch(void* const* d_in, const int* in_sizes, int n_in,
                              void* d_out, int out_size) {
    const float* q  = (const float*)d_in[0];
    const float* k  = (const float*)d_in[1];
    const float* v  = (const float*)d_in[2];
    const unsigned char* pad = (const unsigned char*)d_in[3];
    const float* Wq = (const float*)d_in[4];
    const float* bq = (const float*)d_in[5];
    const float* Wk = (const float*)d_in[6];
    const float* bk = (const float*)d_in[7];
    const float* Wv = (const float*)d_in[8];
    const float* bv = (const float*)d_in[9];
    const float* Wo = (const float*)d_in[10];
    const float* bo = (const float*)d_in[11];
    float* out = (float*)d_out;

    float *p_qpe, *p_kpe, *p_Qh, *p_Kh, *p_Vh, *p_attn;
    cudaGetSymbolAddress((void**)&p_qpe,  g_qpe);
    cudaGetSymbolAddress((void**)&p_kpe,  g_kpe);
    cudaGetSymbolAddress((void**)&p_Qh,   g_Qh);
    cudaGetSymbolAddress((void**)&p_Kh,   g_Kh);
    cudaGetSymbolAddress((void**)&p_Vh,   g_Vh);
    cudaGetSymbolAddress((void**)&p_attn, g_attn);

    cudaFuncSetAttribute(attn_tf32, cudaFuncAttributeMaxDynamicSharedMemorySize, ATTN_SMEM);

    // 1) positional encodings
    int pe_threads = M_ * (D_ / 2);
    pe_add_kernel<<<(pe_threads + 255) / 256, 256>>>(q, k);

    // 2) QKV projections -> head layout
    dim3 gg(D_ / 128, M_ / 128), blk(256);
    gemm_tf32<1><<<gg, blk>>>(p_qpe, Wq, bq, p_Qh);
    gemm_tf32<1><<<gg, blk>>>(p_kpe, Wk, bk, p_Kh);
    gemm_tf32<1><<<gg, blk>>>(v,     Wv, bv, p_Vh);

    // 3) fused causal attention (tf32 tensor cores)
    attn_tf32<<<dim3(L_ / 128, B_ * H_), 256, ATTN_SMEM>>>(pad, p_attn);

    // 4) output projection
    gemm_tf32<0><<<gg, blk>>>(p_attn, Wo, bo, out);
}